// round 12
// baseline (speedup 1.0000x reference)
#include <cuda_runtime.h>
#include <cuda_bf16.h>
#include <math.h>

#define NTOT 65536
#define L_CH 128
#define WARMUP 48
#define NCH (NTOT / L_CH)   // 512

#define SB 64     // sort blocks
#define ST 1024   // sort threads per block (1 item/thread)

// ---------------- static scratch (no allocations allowed) ----------------
__device__ unsigned int g_keys[NTOT];
__device__ unsigned int g_keys2[NTOT];
__device__ unsigned int g_idx[NTOT];
__device__ unsigned int g_idx2[NTOT];
__device__ unsigned int g_hist[4 * 256 * SB];  // [pass][digit*SB + block]
__device__ float g_x[NTOT * 8];                // sorted-order features
__device__ float g_ys[2 * NTOT * 16];          // raw scan outputs (dir, sortedpos, i)
__device__ float g_ctx[2 * NTOT * 8];          // fwd/bwd ctx in ORIGINAL order

// ---------------- kernel 1: keys + identity perm + pass-0 histogram ----------------
__global__ void __launch_bounds__(ST) prep_kernel(const float* __restrict__ g,
                                                  unsigned int* __restrict__ keys,
                                                  unsigned int* __restrict__ vals,
                                                  unsigned int* __restrict__ hist0) {
    __shared__ unsigned int sh[256];
    int t = threadIdx.x, b = blockIdx.x;
    if (t < 256) sh[t] = 0;
    __syncthreads();
    int n = b * ST + t;
    unsigned int k = __float_as_uint(g[n]) & 0x7fffffffu;  // |g| bits sort as uint
    keys[n] = k;
    vals[n] = (unsigned)n;
    atomicAdd(&sh[k & 255u], 1u);
    __syncthreads();
    if (t < 256) hist0[t * SB + b] = sh[t];   // exclusive (digit,block) slot: plain store
}

// ---------------- sort: exclusive scan of one pass's 16384-entry histogram ----------------
__global__ void __launch_bounds__(ST) scan_hist_kernel(unsigned int* __restrict__ h) {
    __shared__ unsigned int warpsum[32];
    int t = threadIdx.x, lane = t & 31, wid = t >> 5;
    unsigned int v[16];
    int base = t * 16;
#pragma unroll
    for (int q = 0; q < 16; q++) v[q] = h[base + q];
    unsigned int run = 0;
#pragma unroll
    for (int q = 0; q < 16; q++) { unsigned int tmp = v[q]; v[q] = run; run += tmp; }
    unsigned int ws = run;   // inclusive warp scan of chunk totals
#pragma unroll
    for (int d = 1; d < 32; d <<= 1) {
        unsigned int x = __shfl_up_sync(0xffffffffu, ws, d);
        if (lane >= d) ws += x;
    }
    if (lane == 31) warpsum[wid] = ws;
    __syncthreads();
    if (wid == 0) {
        unsigned int w = warpsum[lane];
#pragma unroll
        for (int d = 1; d < 32; d <<= 1) {
            unsigned int x = __shfl_up_sync(0xffffffffu, w, d);
            if (lane >= d) w += x;
        }
        warpsum[lane] = w;   // inclusive
    }
    __syncthreads();
    unsigned int offset = (ws - run) + (wid ? warpsum[wid - 1] : 0u);
#pragma unroll
    for (int q = 0; q < 16; q++) h[base + q] = v[q] + offset;
}

// ---------------- sort: stable scatter (+ fused next-pass histogram) ----------------
__global__ void __launch_bounds__(ST) scatter_kernel(
    const unsigned int* __restrict__ kin, const unsigned int* __restrict__ vin,
    unsigned int* __restrict__ kout, unsigned int* __restrict__ vout,
    const unsigned int* __restrict__ basehist, unsigned int* __restrict__ nexthist,
    int shift, int nextshift) {
    __shared__ unsigned int wh[32 * 256];   // [warp][digit], 32KB
    int t = threadIdx.x, b = blockIdx.x;
    int lane = t & 31, warp = t >> 5;
    for (int q = t; q < 32 * 256; q += ST) wh[q] = 0;
    __syncthreads();
    int n = b * ST + t;
    unsigned int k = kin[n], v = vin[n];
    unsigned int d = (k >> shift) & 255u;
    unsigned int mask = __match_any_sync(0xffffffffu, d);
    unsigned int rank = __popc(mask & ((1u << lane) - 1u));
    unsigned int cnt = __popc(mask);
    if (rank == 0) wh[warp * 256 + d] = cnt;   // leader writes warp count
    __syncthreads();
    if (t < 256) {   // exclusive warp-prefix per digit
        unsigned int run = 0;
#pragma unroll
        for (int w = 0; w < 32; w++) {
            unsigned int c = wh[w * 256 + t];
            wh[w * 256 + t] = run;
            run += c;
        }
    }
    __syncthreads();
    unsigned int pos = basehist[d * SB + b] + wh[warp * 256 + d] + rank;
    kout[pos] = k;
    vout[pos] = v;
    if (nexthist) {   // build next pass's per-(digit, output-block) histogram
        unsigned int nd = (k >> nextshift) & 255u;
        atomicAdd(&nexthist[nd * SB + (pos >> 10)], 1u);
    }
}

// ---------------- kernel 2: x = [gs, ss] @ inproj_W.T + b (sorted order) ----------------
__global__ void xproj_kernel(const float* __restrict__ g, const float* __restrict__ s,
                             const unsigned int* __restrict__ sidx,
                             const float* __restrict__ W, const float* __restrict__ b,
                             float* __restrict__ x) {
    int k = blockIdx.x * blockDim.x + threadIdx.x;
    int o = sidx[k];
    float gv = g[o], sv = s[o];
#pragma unroll
    for (int m = 0; m < 8; m++)
        x[k * 8 + m] = fmaf(gv, W[m * 2 + 0], fmaf(sv, W[m * 2 + 1], b[m]));
}

// ---------------- kernel 3: chunked warmup Mamba scan (both directions) ----------------
__global__ void __launch_bounds__(256) scan_kernel(
    const float* __restrict__ x,
    const float* __restrict__ inW,   // (2,32,8)
    const float* __restrict__ dtW,   // (2,16,16)
    const float* __restrict__ dtb,   // (2,16)
    const float* __restrict__ BW,    // (2,16,16)
    const float* __restrict__ CW,    // (2,16,16)
    const float* __restrict__ Alog,  // (2,16,16)
    const float* __restrict__ rope,  // (2,16,16)
    const float* __restrict__ h0f, const float* __restrict__ h0b,
    float* __restrict__ ys,          // (2,N,16)
    float* __restrict__ hfin)        // 512 floats: new_fwd then new_bwd
{
    const int dir = blockIdx.y;
    const int chunk = blockIdx.x;
    const int tid = threadIdx.x;
    const int i = tid >> 4, j = tid & 15;
    const int lane = tid & 31;
    const int srcRot = (lane & 16) | ((lane + 15) & 15);  // j-1 mod 16 within 16-lane group

    __shared__ float s_inWx[8][16];   // [m][i]
    __shared__ float s_dtWT[16][16];  // [k][i]
    __shared__ float s_BWT[16][16];   // [k][j]
    __shared__ float s_CWT[16][16];
    __shared__ float s_dtb[16];
    __shared__ float sx[16][8];
    __shared__ float sxb[16][16];
    __shared__ float sdt[16][16];
    __shared__ float sdxb[16][16];
    __shared__ float sB[16][16];
    __shared__ float sC[16][16];
    __shared__ float sh[16][16][17];  // padded: conflict-free write(t,i,j) & read(j-loop)

    if (tid < 128) { int m = tid >> 4, c = tid & 15; s_inWx[m][c] = inW[dir * 256 + c * 8 + m]; }
    { int k = tid >> 4, c = tid & 15;
      s_dtWT[k][c] = dtW[dir * 256 + c * 16 + k];
      s_BWT[k][c]  = BW [dir * 256 + c * 16 + k];
      s_CWT[k][c]  = CW [dir * 256 + c * 16 + k]; }
    if (tid < 16) s_dtb[tid] = dtb[dir * 16 + tid];

    const float Ac = -__expf(Alog[dir * 256 + tid]);
    const float Rc = rope[dir * 256 + tid];

    int g0 = chunk * L_CH - WARMUP;
    float h;
    if (g0 <= 0) { g0 = 0; h = (dir == 0 ? h0f : h0b)[tid]; }  // exact initial state
    else h = 0.0f;                                             // warmup (state decays)
    const int gend = (chunk + 1) * L_CH;
    const int outStart = chunk * L_CH;

    const int xt = tid >> 3, xm = tid & 7;   // staging role for tid<128
    float xr = 0.0f;
    if (tid < 128) {
        int p = (dir == 0) ? (g0 + xt) : (NTOT - 1 - (g0 + xt));
        xr = x[p * 8 + xm];
    }
    __syncthreads();

    for (int base = g0; base < gend; base += 16) {
        const bool doOut = (base >= outStart);   // block-uniform
        if (tid < 128) sx[xt][xm] = xr;
        __syncthreads();                                         // S1
        {   // xb projection
            int t = tid >> 4, c = tid & 15;
            float acc = 0.0f;
#pragma unroll
            for (int m = 0; m < 8; m++) acc = fmaf(sx[t][m], s_inWx[m][c], acc);
            sxb[t][c] = acc;
        }
        __syncthreads();                                         // S2
        {   // dt / B (+C for output tiles) projections
            int t = tid >> 4, c = tid & 15;
            float u = s_dtb[c], bv = 0.0f;
#pragma unroll
            for (int k = 0; k < 16; k++) {
                float xbk = sxb[t][k];
                u  = fmaf(xbk, s_dtWT[k][c], u);
                bv = fmaf(xbk, s_BWT[k][c], bv);
            }
            // fast softplus: MUFU exp+log; u>15 branch keeps overflow exact
            float dt = (u > 15.0f) ? u : __logf(1.0f + __expf(u));
            sdt[t][c] = dt;
            sdxb[t][c] = dt * sxb[t][c];
            sB[t][c] = bv;
            if (doOut) {
                float cv = 0.0f;
#pragma unroll
                for (int k = 0; k < 16; k++) cv = fmaf(sxb[t][k], s_CWT[k][c], cv);
                sC[t][c] = cv;
            }
        }
        // prefetch next tile's x (latency hidden behind phases B/C/D)
        if (tid < 128 && base + 16 < gend) {
            int p = (dir == 0) ? (base + 16 + xt) : (NTOT - 1 - (base + 16 + xt));
            xr = x[p * 8 + xm];
        }
        __syncthreads();                                         // S3
        // ---- phases B+C in two 8-step halves (low register pressure) ----
#pragma unroll
        for (int half = 0; half < 2; half++) {
            float ca[8], cb[8], db[8];
#pragma unroll
            for (int tt = 0; tt < 8; tt++) {
                int t = half * 8 + tt;
                float dt = sdt[t][i];
                float ph = dt * Rc;
                float sn, cs;
                __sincosf(ph, &sn, &cs);        // |ph| small: abs err ~2^-21
                float xA  = dt * Ac;
                float num = fmaf(0.5f, xA, 1.0f);
                float den = fmaf(-0.5f, xA, 1.0f + 1e-8f);
                float t_r = __fdividef(num, den);
                ca[tt] = cs * t_r;
                cb[tt] = sn * t_r;
                db[tt] = sdxb[t][i] * sB[t][j];
            }
            if (doOut) {
#pragma unroll
                for (int tt = 0; tt < 8; tt++) {
                    float hm1 = __shfl_sync(0xffffffffu, h, srcRot);
                    h = fmaf(ca[tt], h, fmaf(-cb[tt], hm1, db[tt]));
                    sh[half * 8 + tt][i][j] = h;
                }
            } else {
#pragma unroll
                for (int tt = 0; tt < 8; tt++) {
                    float hm1 = __shfl_sync(0xffffffffu, h, srcRot);
                    h = fmaf(ca[tt], h, fmaf(-cb[tt], hm1, db[tt]));
                }
            }
        }
        if (doOut) {
            __syncthreads();                                     // S4
            // ---- phase D: y = sum_j h*C, fully parallel ----
            int t = tid >> 4, ii = tid & 15;
            float acc = 0.0f;
#pragma unroll
            for (int jj = 0; jj < 16; jj++)
                acc = fmaf(sh[t][ii][jj], sC[t][jj], acc);
            int p = (dir == 0) ? (base + t) : (NTOT - 1 - (base + t));
            ys[((size_t)dir * NTOT + p) * 16 + ii] = acc;
        }
        // no trailing sync: next tile's S1 orders all cross-tile hazards
    }
    if (chunk == NCH - 1) hfin[dir * 256 + tid] = h;  // final states (outputs)
}

// ---------------- kernel 4: epilogue projections + scatter to original order ----------------
__global__ void post_kernel(const float* __restrict__ x, const float* __restrict__ ys,
                            const unsigned int* __restrict__ sidx,
                            const float* __restrict__ inW, const float* __restrict__ D,
                            const float* __restrict__ outW, float* __restrict__ ctx) {
    int k = blockIdx.x * blockDim.x + threadIdx.x;
    float4 xv0 = ((const float4*)x)[k * 2 + 0];
    float4 xv1 = ((const float4*)x)[k * 2 + 1];
    float xv[8] = {xv0.x, xv0.y, xv0.z, xv0.w, xv1.x, xv1.y, xv1.z, xv1.w};
    int o = sidx[k];
#pragma unroll
    for (int d = 0; d < 2; d++) {
        float yv[16];
#pragma unroll
        for (int q = 0; q < 4; q++) {
            float4 y4 = ((const float4*)ys)[((size_t)d * NTOT + k) * 4 + q];
            yv[q * 4 + 0] = y4.x; yv[q * 4 + 1] = y4.y;
            yv[q * 4 + 2] = y4.z; yv[q * 4 + 3] = y4.w;
        }
        float out[8];
#pragma unroll
        for (int m = 0; m < 8; m++) out[m] = 0.0f;
#pragma unroll
        for (int ii = 0; ii < 16; ii++) {
            float xb = 0.0f, z = 0.0f;
#pragma unroll
            for (int m = 0; m < 8; m++) {
                xb = fmaf(xv[m], inW[d * 256 + ii * 8 + m], xb);
                z  = fmaf(xv[m], inW[d * 256 + (16 + ii) * 8 + m], z);
            }
            float sg = __fdividef(1.0f, 1.0f + __expf(-z));
            float yi = fmaf(yv[ii], z * sg, D[d * 16 + ii] * xb);
#pragma unroll
            for (int m = 0; m < 8; m++)
                out[m] = fmaf(yi, outW[d * 128 + m * 16 + ii], out[m]);
        }
        float4* cbase = (float4*)&ctx[((size_t)d * NTOT + o) * 8];
        cbase[0] = make_float4(out[0], out[1], out[2], out[3]);
        cbase[1] = make_float4(out[4], out[5], out[6], out[7]);
    }
}

// ---------------- kernel 5: GRU + PEER routing/experts + final combine ----------------
__global__ void __launch_bounds__(256) gp_kernel(
    const float* __restrict__ g, const float* __restrict__ s,
    const float* __restrict__ gru0, const float* __restrict__ ctx,
    const float* __restrict__ Wz, const float* __restrict__ bz,
    const float* __restrict__ Wr, const float* __restrict__ br,
    const float* __restrict__ Wh, const float* __restrict__ bh,
    const float* __restrict__ qW, const float* __restrict__ kA, const float* __restrict__ kB,
    const float* __restrict__ eW1, const float* __restrict__ eb1,
    const float* __restrict__ eW2, const float* __restrict__ eb2,
    float* __restrict__ out) {
    __shared__ float sWz[88], sWr[88], sWh[88], sbz[4], sbr[4], sbh[4];
    __shared__ float sqW[704];       // (4,8,22)
    __shared__ float skA[192], skB[192];
    __shared__ float seW1[144 * 17], seb1[144 * 17], seW2[144 * 17];  // pad vs bank conflicts
    __shared__ float seb2[144];

    int tid = threadIdx.x;
    for (int q = tid; q < 88; q += 256) { sWz[q] = Wz[q]; sWr[q] = Wr[q]; sWh[q] = Wh[q]; }
    if (tid < 4) { sbz[tid] = bz[tid]; sbr[tid] = br[tid]; sbh[tid] = bh[tid]; }
    for (int q = tid; q < 704; q += 256) sqW[q] = qW[q];
    for (int q = tid; q < 192; q += 256) { skA[q] = kA[q]; skB[q] = kB[q]; }
    for (int q = tid; q < 2304; q += 256) {
        int e = q >> 4, eh = q & 15;
        seW1[e * 17 + eh] = eW1[q];
        seb1[e * 17 + eh] = eb1[q];
        seW2[e * 17 + eh] = eW2[q];
    }
    for (int q = tid; q < 144; q += 256) seb2[q] = eb2[q];
    __syncthreads();

    int n = blockIdx.x * blockDim.x + tid;
    float gv = g[n], sv = s[n];
    float xin[18];
    xin[0] = gv; xin[1] = sv;
#pragma unroll
    for (int m = 0; m < 8; m++) { xin[2 + m] = ctx[(size_t)n * 8 + m]; xin[10 + m] = ctx[(size_t)(NTOT + n) * 8 + m]; }
    float hv[4];
#pragma unroll
    for (int c = 0; c < 4; c++) hv[c] = gru0[n * 4 + c];

    float zg[4], rr[4];
#pragma unroll
    for (int c = 0; c < 4; c++) {
        float az = sbz[c], ar = sbr[c];
#pragma unroll
        for (int q = 0; q < 18; q++) { az = fmaf(xin[q], sWz[c * 22 + q], az); ar = fmaf(xin[q], sWr[c * 22 + q], ar); }
#pragma unroll
        for (int q = 0; q < 4; q++) { az = fmaf(hv[q], sWz[c * 22 + 18 + q], az); ar = fmaf(hv[q], sWr[c * 22 + 18 + q], ar); }
        zg[c] = __fdividef(1.0f, 1.0f + __expf(-az));
        rr[c] = __fdividef(1.0f, 1.0f + __expf(-ar));
    }
    float ng[4];
#pragma unroll
    for (int c = 0; c < 4; c++) {
        float ah = sbh[c];
#pragma unroll
        for (int q = 0; q < 18; q++) ah = fmaf(xin[q], sWh[c * 22 + q], ah);
#pragma unroll
        for (int q = 0; q < 4; q++) ah = fmaf(rr[q] * hv[q], sWh[c * 22 + 18 + q], ah);
        float ht = tanhf(ah);
        ng[c] = fmaf(zg[c], ht - hv[c], hv[c]);
        out[NTOT + n * 4 + c] = ng[c];
    }

    float pin[22];
#pragma unroll
    for (int c = 0; c < 4; c++) pin[c] = ng[c];
#pragma unroll
    for (int m = 0; m < 16; m++) pin[4 + m] = xin[2 + m];
    pin[20] = gv; pin[21] = sv;

    float tot = 0.0f;
#pragma unroll
    for (int hd = 0; hd < 4; hd++) {
        float q[8];
#pragma unroll
        for (int m = 0; m < 8; m++) {
            float a = 0.0f;
#pragma unroll
            for (int qq = 0; qq < 22; qq++) a = fmaf(pin[qq], sqW[hd * 176 + m * 22 + qq], a);
            q[m] = a;
        }
        int ia = 0, ib = 0;
        float ba = -3.4e38f, bb = -3.4e38f;
#pragma unroll
        for (int p = 0; p < 12; p++) {
            float sa = q[0] * skA[hd * 48 + p * 4 + 0];
            sa = fmaf(q[1], skA[hd * 48 + p * 4 + 1], sa);
            sa = fmaf(q[2], skA[hd * 48 + p * 4 + 2], sa);
            sa = fmaf(q[3], skA[hd * 48 + p * 4 + 3], sa);
            if (sa > ba) { ba = sa; ia = p; }
            float sb = q[4] * skB[hd * 48 + p * 4 + 0];
            sb = fmaf(q[5], skB[hd * 48 + p * 4 + 1], sb);
            sb = fmaf(q[6], skB[hd * 48 + p * 4 + 2], sb);
            sb = fmaf(q[7], skB[hd * 48 + p * 4 + 3], sb);
            if (sb > bb) { bb = sb; ib = p; }
        }
        int e = ia * 12 + ib;
        float acc = seb2[e];
#pragma unroll
        for (int eh = 0; eh < 16; eh++) {
            float z1 = fmaf(seW1[e * 17 + eh], gv, seb1[e * 17 + eh]);
            z1 = fmaxf(z1, 0.0f);
            acc = fmaf(seW2[e * 17 + eh], z1, acc);
        }
        tot += acc;
    }
    out[n] = fmaf(0.1f * 0.25f, tot, gv);  // g + RESCALE * total/NH
}

// ---------------- launch ----------------
extern "C" void kernel_launch(void* const* d_in, const int* in_sizes, int n_in,
                              void* d_out, int out_size) {
    const float* grad      = (const float*)d_in[0];
    const float* sharp     = (const float*)d_in[1];
    const float* gru_state = (const float*)d_in[2];
    const float* mfwd      = (const float*)d_in[3];
    const float* mbwd      = (const float*)d_in[4];
    const float* inproj_W  = (const float*)d_in[5];
    const float* inproj_b  = (const float*)d_in[6];
    const float* m_inW     = (const float*)d_in[7];
    const float* m_dtW     = (const float*)d_in[8];
    const float* m_dtb     = (const float*)d_in[9];
    const float* m_BW      = (const float*)d_in[10];
    const float* m_CW      = (const float*)d_in[11];
    const float* m_Alog    = (const float*)d_in[12];
    const float* m_D       = (const float*)d_in[13];
    const float* m_rope    = (const float*)d_in[14];
    const float* m_outW    = (const float*)d_in[15];
    const float* gru_Wz    = (const float*)d_in[16];
    const float* gru_bz    = (const float*)d_in[17];
    const float* gru_Wr    = (const float*)d_in[18];
    const float* gru_br    = (const float*)d_in[19];
    const float* gru_Wh    = (const float*)d_in[20];
    const float* gru_bh    = (const float*)d_in[21];
    const float* peer_qW   = (const float*)d_in[22];
    const float* keysA     = (const float*)d_in[23];
    const float* keysB     = (const float*)d_in[24];
    const float* eW1       = (const float*)d_in[25];
    const float* eb1       = (const float*)d_in[26];
    const float* eW2       = (const float*)d_in[27];
    const float* eb2       = (const float*)d_in[28];
    float* out = (float*)d_out;

    unsigned int *ki, *ko, *vi, *vo, *hist;
    float *xbuf, *ysbuf, *ctxbuf;
    cudaGetSymbolAddress((void**)&ki, g_keys);
    cudaGetSymbolAddress((void**)&ko, g_keys2);
    cudaGetSymbolAddress((void**)&vi, g_idx);
    cudaGetSymbolAddress((void**)&vo, g_idx2);
    cudaGetSymbolAddress((void**)&hist, g_hist);
    cudaGetSymbolAddress((void**)&xbuf, g_x);
    cudaGetSymbolAddress((void**)&ysbuf, g_ys);
    cudaGetSymbolAddress((void**)&ctxbuf, g_ctx);

    unsigned int* h0 = hist + 0 * 256 * SB;
    unsigned int* h1 = hist + 1 * 256 * SB;
    unsigned int* h2 = hist + 2 * 256 * SB;
    unsigned int* h3 = hist + 3 * 256 * SB;

    // ---- custom stable LSD radix sort (4x8-bit), full-chip parallel ----
    cudaMemsetAsync(hist, 0, 4 * 256 * SB * sizeof(unsigned int), (cudaStream_t)0);
    prep_kernel<<<SB, ST>>>(grad, ki, vi, h0);
    scan_hist_kernel<<<1, ST>>>(h0);
    scatter_kernel<<<SB, ST>>>(ki, vi, ko, vo, h0, h1, 0, 8);
    scan_hist_kernel<<<1, ST>>>(h1);
    scatter_kernel<<<SB, ST>>>(ko, vo, ki, vi, h1, h2, 8, 16);
    scan_hist_kernel<<<1, ST>>>(h2);
    scatter_kernel<<<SB, ST>>>(ki, vi, ko, vo, h2, h3, 16, 24);
    scan_hist_kernel<<<1, ST>>>(h3);
    scatter_kernel<<<SB, ST>>>(ko, vo, ki, vi, h3, nullptr, 24, 0);
    // sorted permutation now in vi (g_idx)

    xproj_kernel<<<NTOT / 256, 256>>>(grad, sharp, vi, inproj_W, inproj_b, xbuf);

    scan_kernel<<<dim3(NCH, 2), 256>>>(xbuf, m_inW, m_dtW, m_dtb, m_BW, m_CW,
                                       m_Alog, m_rope, mfwd, mbwd, ysbuf,
                                       out + 5 * NTOT);

    post_kernel<<<NTOT / 256, 256>>>(xbuf, ysbuf, vi, m_inW, m_D, m_outW, ctxbuf);

    gp_kernel<<<NTOT / 256, 256>>>(grad, sharp, gru_state, ctxbuf,
                                   gru_Wz, gru_bz, gru_Wr, gru_br, gru_Wh, gru_bh,
                                   peer_qW, keysA, keysB, eW1, eb1, eW2, eb2, out);

    (void)in_sizes; (void)n_in; (void)out_size;
}

// round 13
// speedup vs baseline: 1.7971x; 1.7971x over previous
#include <cuda_runtime.h>
#include <cuda_bf16.h>
#include <cub/cub.cuh>
#include <math.h>

#define NTOT 65536
#define L_CH 128
#define WARMUP 48
#define NCH (NTOT / L_CH)   // 512

// ---------------- static scratch (no allocations allowed) ----------------
__device__ unsigned int g_keys[NTOT];
__device__ unsigned int g_keys2[NTOT];
__device__ unsigned int g_idx[NTOT];
__device__ unsigned int g_idx2[NTOT];
__device__ unsigned char g_cubtemp[1 << 23];   // 8 MB, plenty for 64K pairs
__device__ float g_x[NTOT * 8];                // sorted-order features
__device__ float g_ys[2 * NTOT * 16];          // raw scan outputs (dir, sortedpos, i)
__device__ float g_ctx[2 * NTOT * 8];          // fwd/bwd ctx in ORIGINAL order

// ---------------- kernel 1: sort keys ----------------
__global__ void prep_kernel(const float* __restrict__ g,
                            unsigned int* __restrict__ keys,
                            unsigned int* __restrict__ vals) {
    int n = blockIdx.x * blockDim.x + threadIdx.x;
    keys[n] = __float_as_uint(g[n]) & 0x7fffffffu;  // |g| bits sort as uint
    vals[n] = (unsigned)n;
}

// ---------------- kernel 2: x = [gs, ss] @ inproj_W.T + b (sorted order) ----------------
__global__ void xproj_kernel(const float* __restrict__ g, const float* __restrict__ s,
                             const unsigned int* __restrict__ sidx,
                             const float* __restrict__ W, const float* __restrict__ b,
                             float* __restrict__ x) {
    int k = blockIdx.x * blockDim.x + threadIdx.x;
    int o = sidx[k];
    float gv = g[o], sv = s[o];
#pragma unroll
    for (int m = 0; m < 8; m++)
        x[k * 8 + m] = fmaf(gv, W[m * 2 + 0], fmaf(sv, W[m * 2 + 1], b[m]));
}

// ---------------- kernel 3: chunked warmup Mamba scan (both directions) ----------------
// Per 16-step tile:
//   A) parallel projections (xb, dt, B[, C]) with 256 threads as (t,c)
//   B) per-(i,j) 2-STEP COMBINED coefficients: h(t+1) = A·h + B·h[j-1] + C·h[j-2] + D
//      (all h-independent; neighbor base-coefs fetched by shfl, off the chain)
//   C) recurrence advances 2 steps per round: 2 overlapped shfls + 3-FMA chain
//      (~19 cyc/step vs 34). Intermediate h(t) for output = 2-FMA side branch.
//   D) parallel y = sum_j h*C from shared (output tiles only)
__global__ void __launch_bounds__(256) scan_kernel(
    const float* __restrict__ x,
    const float* __restrict__ inW,   // (2,32,8)
    const float* __restrict__ dtW,   // (2,16,16)
    const float* __restrict__ dtb,   // (2,16)
    const float* __restrict__ BW,    // (2,16,16)
    const float* __restrict__ CW,    // (2,16,16)
    const float* __restrict__ Alog,  // (2,16,16)
    const float* __restrict__ rope,  // (2,16,16)
    const float* __restrict__ h0f, const float* __restrict__ h0b,
    float* __restrict__ ys,          // (2,N,16)
    float* __restrict__ hfin)        // 512 floats: new_fwd then new_bwd
{
    const int dir = blockIdx.y;
    const int chunk = blockIdx.x;
    const int tid = threadIdx.x;
    const int i = tid >> 4, j = tid & 15;
    const int lane = tid & 31;
    const int srcRot  = (lane & 16) | ((lane + 15) & 15);  // j-1 mod 16 in 16-lane group
    const int srcRot2 = (lane & 16) | ((lane + 14) & 15);  // j-2 mod 16

    __shared__ float s_inWx[8][16];   // [m][i]
    __shared__ float s_dtWT[16][16];  // [k][i]
    __shared__ float s_BWT[16][16];   // [k][j]
    __shared__ float s_CWT[16][16];
    __shared__ float s_dtb[16];
    __shared__ float sx[16][8];
    __shared__ float sxb[16][16];
    __shared__ float sdt[16][16];
    __shared__ float sdxb[16][16];
    __shared__ float sB[16][16];
    __shared__ float sC[16][16];
    __shared__ float sh[16][16][17];  // padded: conflict-free write(t,i,j) & read(j-loop)

    if (tid < 128) { int m = tid >> 4, c = tid & 15; s_inWx[m][c] = inW[dir * 256 + c * 8 + m]; }
    { int k = tid >> 4, c = tid & 15;
      s_dtWT[k][c] = dtW[dir * 256 + c * 16 + k];
      s_BWT[k][c]  = BW [dir * 256 + c * 16 + k];
      s_CWT[k][c]  = CW [dir * 256 + c * 16 + k]; }
    if (tid < 16) s_dtb[tid] = dtb[dir * 16 + tid];

    const float Ac = -__expf(Alog[dir * 256 + tid]);
    const float Rc = rope[dir * 256 + tid];

    int g0 = chunk * L_CH - WARMUP;
    float h;
    if (g0 <= 0) { g0 = 0; h = (dir == 0 ? h0f : h0b)[tid]; }  // exact initial state
    else h = 0.0f;                                             // warmup (state decays)
    const int gend = (chunk + 1) * L_CH;
    const int outStart = chunk * L_CH;

    const int xt = tid >> 3, xm = tid & 7;   // staging role for tid<128
    float xr = 0.0f;
    if (tid < 128) {
        int p = (dir == 0) ? (g0 + xt) : (NTOT - 1 - (g0 + xt));
        xr = x[p * 8 + xm];
    }
    __syncthreads();

    for (int base = g0; base < gend; base += 16) {
        const bool doOut = (base >= outStart);   // block-uniform
        if (tid < 128) sx[xt][xm] = xr;
        __syncthreads();                                         // S1
        {   // xb projection
            int t = tid >> 4, c = tid & 15;
            float acc = 0.0f;
#pragma unroll
            for (int m = 0; m < 8; m++) acc = fmaf(sx[t][m], s_inWx[m][c], acc);
            sxb[t][c] = acc;
        }
        __syncthreads();                                         // S2
        {   // dt / B (+C for output tiles) projections
            int t = tid >> 4, c = tid & 15;
            float u = s_dtb[c], bv = 0.0f;
#pragma unroll
            for (int k = 0; k < 16; k++) {
                float xbk = sxb[t][k];
                u  = fmaf(xbk, s_dtWT[k][c], u);
                bv = fmaf(xbk, s_BWT[k][c], bv);
            }
            // fast softplus: MUFU exp+log; u>15 branch keeps overflow exact
            float dt = (u > 15.0f) ? u : __logf(1.0f + __expf(u));
            sdt[t][c] = dt;
            sdxb[t][c] = dt * sxb[t][c];
            sB[t][c] = bv;
            if (doOut) {
                float cv = 0.0f;
#pragma unroll
                for (int k = 0; k < 16; k++) cv = fmaf(sxb[t][k], s_CWT[k][c], cv);
                sC[t][c] = cv;
            }
        }
        // prefetch next tile's x (latency hidden behind phases B/C/D)
        if (tid < 128 && base + 16 < gend) {
            int p = (dir == 0) ? (base + 16 + xt) : (NTOT - 1 - (base + 16 + xt));
            xr = x[p * 8 + xm];
        }
        __syncthreads();                                         // S3
        // ---- phases B+C in two halves of 4 two-step rounds each ----
#pragma unroll
        for (int half = 0; half < 2; half++) {
            float cA[4], cB[4], cC[4], cD[4];   // 2-step jump coefs
            float a0[4], b0[4], d0[4];          // step-t0 base coefs (side branch)
#pragma unroll
            for (int rr = 0; rr < 4; rr++) {
                int t0 = (half * 4 + rr) * 2, t1 = t0 + 1;
                float dt0 = sdt[t0][i], dt1 = sdt[t1][i];
                float sn0, cs0, sn1, cs1;
                __sincosf(dt0 * Rc, &sn0, &cs0);
                __sincosf(dt1 * Rc, &sn1, &cs1);
                float x0 = dt0 * Ac, x1 = dt1 * Ac;
                float r0 = __fdividef(fmaf(0.5f, x0, 1.0f), fmaf(-0.5f, x0, 1.0f + 1e-8f));
                float r1 = __fdividef(fmaf(0.5f, x1, 1.0f), fmaf(-0.5f, x1, 1.0f + 1e-8f));
                float ca0 = cs0 * r0, cb0 = sn0 * r0;
                float ca1 = cs1 * r1, cb1 = sn1 * r1;
                float db0 = sdxb[t0][i] * sB[t0][j];
                float db1 = sdxb[t1][i] * sB[t1][j];
                float ca0m = __shfl_sync(0xffffffffu, ca0, srcRot);
                float cb0m = __shfl_sync(0xffffffffu, cb0, srcRot);
                float db0m = __shfl_sync(0xffffffffu, db0, srcRot);
                cA[rr] = ca1 * ca0;
                cB[rr] = -fmaf(ca1, cb0, cb1 * ca0m);
                cC[rr] = cb1 * cb0m;
                cD[rr] = fmaf(ca1, db0, fmaf(-cb1, db0m, db1));
                a0[rr] = ca0; b0[rr] = cb0; d0[rr] = db0;
            }
            if (doOut) {
#pragma unroll
                for (int rr = 0; rr < 4; rr++) {
                    float hm1 = __shfl_sync(0xffffffffu, h, srcRot);
                    float hm2 = __shfl_sync(0xffffffffu, h, srcRot2);
                    // side branch: h(t0) for output (off the dependent chain)
                    float hs = fmaf(a0[rr], h, fmaf(-b0[rr], hm1, d0[rr]));
                    // chain: jump 2 steps
                    h = fmaf(cA[rr], h, fmaf(cB[rr], hm1, fmaf(cC[rr], hm2, cD[rr])));
                    int t0 = (half * 4 + rr) * 2;
                    sh[t0][i][j] = hs;
                    sh[t0 + 1][i][j] = h;
                }
            } else {
#pragma unroll
                for (int rr = 0; rr < 4; rr++) {
                    float hm1 = __shfl_sync(0xffffffffu, h, srcRot);
                    float hm2 = __shfl_sync(0xffffffffu, h, srcRot2);
                    h = fmaf(cA[rr], h, fmaf(cB[rr], hm1, fmaf(cC[rr], hm2, cD[rr])));
                }
            }
        }
        if (doOut) {
            __syncthreads();                                     // S4
            // ---- phase D: y = sum_j h*C, fully parallel ----
            int t = tid >> 4, ii = tid & 15;
            float acc = 0.0f;
#pragma unroll
            for (int jj = 0; jj < 16; jj++)
                acc = fmaf(sh[t][ii][jj], sC[t][jj], acc);
            int p = (dir == 0) ? (base + t) : (NTOT - 1 - (base + t));
            ys[((size_t)dir * NTOT + p) * 16 + ii] = acc;
        }
        // no trailing sync: next tile's S1 orders all cross-tile hazards
    }
    if (chunk == NCH - 1) hfin[dir * 256 + tid] = h;  // final states (outputs)
}

// ---------------- kernel 4: epilogue projections + scatter to original order ----------------
__global__ void post_kernel(const float* __restrict__ x, const float* __restrict__ ys,
                            const unsigned int* __restrict__ sidx,
                            const float* __restrict__ inW, const float* __restrict__ D,
                            const float* __restrict__ outW, float* __restrict__ ctx) {
    int k = blockIdx.x * blockDim.x + threadIdx.x;
    float4 xv0 = ((const float4*)x)[k * 2 + 0];
    float4 xv1 = ((const float4*)x)[k * 2 + 1];
    float xv[8] = {xv0.x, xv0.y, xv0.z, xv0.w, xv1.x, xv1.y, xv1.z, xv1.w};
    int o = sidx[k];
#pragma unroll
    for (int d = 0; d < 2; d++) {
        float yv[16];
#pragma unroll
        for (int q = 0; q < 4; q++) {
            float4 y4 = ((const float4*)ys)[((size_t)d * NTOT + k) * 4 + q];
            yv[q * 4 + 0] = y4.x; yv[q * 4 + 1] = y4.y;
            yv[q * 4 + 2] = y4.z; yv[q * 4 + 3] = y4.w;
        }
        float out[8];
#pragma unroll
        for (int m = 0; m < 8; m++) out[m] = 0.0f;
#pragma unroll
        for (int ii = 0; ii < 16; ii++) {
            float xb = 0.0f, z = 0.0f;
#pragma unroll
            for (int m = 0; m < 8; m++) {
                xb = fmaf(xv[m], inW[d * 256 + ii * 8 + m], xb);
                z  = fmaf(xv[m], inW[d * 256 + (16 + ii) * 8 + m], z);
            }
            float sg = __fdividef(1.0f, 1.0f + __expf(-z));
            float yi = fmaf(yv[ii], z * sg, D[d * 16 + ii] * xb);
#pragma unroll
            for (int m = 0; m < 8; m++)
                out[m] = fmaf(yi, outW[d * 128 + m * 16 + ii], out[m]);
        }
        float4* cbase = (float4*)&ctx[((size_t)d * NTOT + o) * 8];
        cbase[0] = make_float4(out[0], out[1], out[2], out[3]);
        cbase[1] = make_float4(out[4], out[5], out[6], out[7]);
    }
}

// ---------------- kernel 5: GRU + PEER routing/experts + final combine ----------------
__global__ void __launch_bounds__(256) gp_kernel(
    const float* __restrict__ g, const float* __restrict__ s,
    const float* __restrict__ gru0, const float* __restrict__ ctx,
    const float* __restrict__ Wz, const float* __restrict__ bz,
    const float* __restrict__ Wr, const float* __restrict__ br,
    const float* __restrict__ Wh, const float* __restrict__ bh,
    const float* __restrict__ qW, const float* __restrict__ kA, const float* __restrict__ kB,
    const float* __restrict__ eW1, const float* __restrict__ eb1,
    const float* __restrict__ eW2, const float* __restrict__ eb2,
    float* __restrict__ out) {
    __shared__ float sWz[88], sWr[88], sWh[88], sbz[4], sbr[4], sbh[4];
    __shared__ float sqW[704];       // (4,8,22)
    __shared__ float skA[192], skB[192];
    __shared__ float seW1[144 * 17], seb1[144 * 17], seW2[144 * 17];  // pad vs bank conflicts
    __shared__ float seb2[144];

    int tid = threadIdx.x;
    for (int q = tid; q < 88; q += 256) { sWz[q] = Wz[q]; sWr[q] = Wr[q]; sWh[q] = Wh[q]; }
    if (tid < 4) { sbz[tid] = bz[tid]; sbr[tid] = br[tid]; sbh[tid] = bh[tid]; }
    for (int q = tid; q < 704; q += 256) sqW[q] = qW[q];
    for (int q = tid; q < 192; q += 256) { skA[q] = kA[q]; skB[q] = kB[q]; }
    for (int q = tid; q < 2304; q += 256) {
        int e = q >> 4, eh = q & 15;
        seW1[e * 17 + eh] = eW1[q];
        seb1[e * 17 + eh] = eb1[q];
        seW2[e * 17 + eh] = eW2[q];
    }
    for (int q = tid; q < 144; q += 256) seb2[q] = eb2[q];
    __syncthreads();

    int n = blockIdx.x * blockDim.x + tid;
    float gv = g[n], sv = s[n];
    float xin[18];
    xin[0] = gv; xin[1] = sv;
#pragma unroll
    for (int m = 0; m < 8; m++) { xin[2 + m] = ctx[(size_t)n * 8 + m]; xin[10 + m] = ctx[(size_t)(NTOT + n) * 8 + m]; }
    float hv[4];
#pragma unroll
    for (int c = 0; c < 4; c++) hv[c] = gru0[n * 4 + c];

    float zg[4], rr[4];
#pragma unroll
    for (int c = 0; c < 4; c++) {
        float az = sbz[c], ar = sbr[c];
#pragma unroll
        for (int q = 0; q < 18; q++) { az = fmaf(xin[q], sWz[c * 22 + q], az); ar = fmaf(xin[q], sWr[c * 22 + q], ar); }
#pragma unroll
        for (int q = 0; q < 4; q++) { az = fmaf(hv[q], sWz[c * 22 + 18 + q], az); ar = fmaf(hv[q], sWr[c * 22 + 18 + q], ar); }
        zg[c] = __fdividef(1.0f, 1.0f + __expf(-az));
        rr[c] = __fdividef(1.0f, 1.0f + __expf(-ar));
    }
    float ng[4];
#pragma unroll
    for (int c = 0; c < 4; c++) {
        float ah = sbh[c];
#pragma unroll
        for (int q = 0; q < 18; q++) ah = fmaf(xin[q], sWh[c * 22 + q], ah);
#pragma unroll
        for (int q = 0; q < 4; q++) ah = fmaf(rr[q] * hv[q], sWh[c * 22 + 18 + q], ah);
        float ht = tanhf(ah);
        ng[c] = fmaf(zg[c], ht - hv[c], hv[c]);
        out[NTOT + n * 4 + c] = ng[c];
    }

    float pin[22];
#pragma unroll
    for (int c = 0; c < 4; c++) pin[c] = ng[c];
#pragma unroll
    for (int m = 0; m < 16; m++) pin[4 + m] = xin[2 + m];
    pin[20] = gv; pin[21] = sv;

    float tot = 0.0f;
#pragma unroll
    for (int hd = 0; hd < 4; hd++) {
        float q[8];
#pragma unroll
        for (int m = 0; m < 8; m++) {
            float a = 0.0f;
#pragma unroll
            for (int qq = 0; qq < 22; qq++) a = fmaf(pin[qq], sqW[hd * 176 + m * 22 + qq], a);
            q[m] = a;
        }
        int ia = 0, ib = 0;
        float ba = -3.4e38f, bb = -3.4e38f;
#pragma unroll
        for (int p = 0; p < 12; p++) {
            float sa = q[0] * skA[hd * 48 + p * 4 + 0];
            sa = fmaf(q[1], skA[hd * 48 + p * 4 + 1], sa);
            sa = fmaf(q[2], skA[hd * 48 + p * 4 + 2], sa);
            sa = fmaf(q[3], skA[hd * 48 + p * 4 + 3], sa);
            if (sa > ba) { ba = sa; ia = p; }
            float sb = q[4] * skB[hd * 48 + p * 4 + 0];
            sb = fmaf(q[5], skB[hd * 48 + p * 4 + 1], sb);
            sb = fmaf(q[6], skB[hd * 48 + p * 4 + 2], sb);
            sb = fmaf(q[7], skB[hd * 48 + p * 4 + 3], sb);
            if (sb > bb) { bb = sb; ib = p; }
        }
        int e = ia * 12 + ib;
        float acc = seb2[e];
#pragma unroll
        for (int eh = 0; eh < 16; eh++) {
            float z1 = fmaf(seW1[e * 17 + eh], gv, seb1[e * 17 + eh]);
            z1 = fmaxf(z1, 0.0f);
            acc = fmaf(seW2[e * 17 + eh], z1, acc);
        }
        tot += acc;
    }
    out[n] = fmaf(0.1f * 0.25f, tot, gv);  // g + RESCALE * total/NH
}

// ---------------- launch ----------------
extern "C" void kernel_launch(void* const* d_in, const int* in_sizes, int n_in,
                              void* d_out, int out_size) {
    const float* grad      = (const float*)d_in[0];
    const float* sharp     = (const float*)d_in[1];
    const float* gru_state = (const float*)d_in[2];
    const float* mfwd      = (const float*)d_in[3];
    const float* mbwd      = (const float*)d_in[4];
    const float* inproj_W  = (const float*)d_in[5];
    const float* inproj_b  = (const float*)d_in[6];
    const float* m_inW     = (const float*)d_in[7];
    const float* m_dtW     = (const float*)d_in[8];
    const float* m_dtb     = (const float*)d_in[9];
    const float* m_BW      = (const float*)d_in[10];
    const float* m_CW      = (const float*)d_in[11];
    const float* m_Alog    = (const float*)d_in[12];
    const float* m_D       = (const float*)d_in[13];
    const float* m_rope    = (const float*)d_in[14];
    const float* m_outW    = (const float*)d_in[15];
    const float* gru_Wz    = (const float*)d_in[16];
    const float* gru_bz    = (const float*)d_in[17];
    const float* gru_Wr    = (const float*)d_in[18];
    const float* gru_br    = (const float*)d_in[19];
    const float* gru_Wh    = (const float*)d_in[20];
    const float* gru_bh    = (const float*)d_in[21];
    const float* peer_qW   = (const float*)d_in[22];
    const float* keysA     = (const float*)d_in[23];
    const float* keysB     = (const float*)d_in[24];
    const float* eW1       = (const float*)d_in[25];
    const float* eb1       = (const float*)d_in[26];
    const float* eW2       = (const float*)d_in[27];
    const float* eb2       = (const float*)d_in[28];
    float* out = (float*)d_out;

    unsigned int *ki, *ko, *vi, *vo;
    void* tmp;
    float *xbuf, *ysbuf, *ctxbuf;
    cudaGetSymbolAddress((void**)&ki, g_keys);
    cudaGetSymbolAddress((void**)&ko, g_keys2);
    cudaGetSymbolAddress((void**)&vi, g_idx);
    cudaGetSymbolAddress((void**)&vo, g_idx2);
    cudaGetSymbolAddress(&tmp, g_cubtemp);
    cudaGetSymbolAddress((void**)&xbuf, g_x);
    cudaGetSymbolAddress((void**)&ysbuf, g_ys);
    cudaGetSymbolAddress((void**)&ctxbuf, g_ctx);

    prep_kernel<<<NTOT / 256, 256>>>(grad, ki, vi);

    // FULL 32-bit stable sort via CUB (custom sort regressed: single-block
    // histogram scans + low-occupancy scatters cost 3x CUB's total).
    size_t temp_bytes = sizeof(g_cubtemp);
    cub::DeviceRadixSort::SortPairs(tmp, temp_bytes, ki, ko, vi, vo, NTOT, 0, 32,
                                    (cudaStream_t)0);

    xproj_kernel<<<NTOT / 256, 256>>>(grad, sharp, vo, inproj_W, inproj_b, xbuf);

    scan_kernel<<<dim3(NCH, 2), 256>>>(xbuf, m_inW, m_dtW, m_dtb, m_BW, m_CW,
                                       m_Alog, m_rope, mfwd, mbwd, ysbuf,
                                       out + 5 * NTOT);

    post_kernel<<<NTOT / 256, 256>>>(xbuf, ysbuf, vo, m_inW, m_D, m_outW, ctxbuf);

    gp_kernel<<<NTOT / 256, 256>>>(grad, sharp, gru_state, ctxbuf,
                                   gru_Wz, gru_bz, gru_Wr, gru_br, gru_Wh, gru_bh,
                                   peer_qW, keysA, keysB, eW1, eb1, eW2, eb2, out);

    (void)in_sizes; (void)n_in; (void)out_size;
}

// round 15
// speedup vs baseline: 1.8163x; 1.0107x over previous
#include <cuda_runtime.h>
#include <cuda_bf16.h>
#include <cub/cub.cuh>
#include <math.h>

#define NTOT 65536
#define L_CH 256
#define WARMUP 48
#define NCH (NTOT / L_CH)   // 256

// ---------------- static scratch (no allocations allowed) ----------------
__device__ unsigned int g_keys[NTOT];
__device__ unsigned int g_keys2[NTOT];
__device__ unsigned int g_idx[NTOT];
__device__ unsigned int g_idx2[NTOT];
__device__ unsigned char g_cubtemp[1 << 23];   // 8 MB, plenty for 64K pairs
__device__ float g_x[NTOT * 8];                // sorted-order features
__device__ float g_ys[2 * NTOT * 16];          // raw scan outputs (dir, sortedpos, i)

// ---------------- kernel 1: sort keys ----------------
__global__ void prep_kernel(const float* __restrict__ g,
                            unsigned int* __restrict__ keys,
                            unsigned int* __restrict__ vals) {
    int n = blockIdx.x * blockDim.x + threadIdx.x;
    keys[n] = __float_as_uint(g[n]) & 0x7fffffffu;  // |g| bits sort as uint
    vals[n] = (unsigned)n;
}

// ---------------- kernel 2: x = [gs, ss] @ inproj_W.T + b (sorted order) ----------------
__global__ void xproj_kernel(const float* __restrict__ g, const float* __restrict__ s,
                             const unsigned int* __restrict__ sidx,
                             const float* __restrict__ W, const float* __restrict__ b,
                             float* __restrict__ x) {
    int k = blockIdx.x * blockDim.x + threadIdx.x;
    int o = sidx[k];
    float gv = g[o], sv = s[o];
#pragma unroll
    for (int m = 0; m < 8; m++)
        x[k * 8 + m] = fmaf(gv, W[m * 2 + 0], fmaf(sv, W[m * 2 + 1], b[m]));
}

// ---------------- kernel 3: chunked warmup Mamba scan (both directions) ----------------
// Per 16-step tile:
//   A) parallel projections (xb, dt, B[, C]) with 256 threads as (t,c)
//   B) per-(i,j) 2-STEP COMBINED coefficients: h(t+1) = A·h + B·h[j-1] + C·h[j-2] + D
//   C) recurrence advances 2 steps per round (2 overlapped shfls + 3-FMA chain);
//      intermediate h(t) for output = side branch
//   D) parallel y = sum_j h*C from shared (output tiles only)
__global__ void __launch_bounds__(256) scan_kernel(
    const float* __restrict__ x,
    const float* __restrict__ inW,   // (2,32,8)
    const float* __restrict__ dtW,   // (2,16,16)
    const float* __restrict__ dtb,   // (2,16)
    const float* __restrict__ BW,    // (2,16,16)
    const float* __restrict__ CW,    // (2,16,16)
    const float* __restrict__ Alog,  // (2,16,16)
    const float* __restrict__ rope,  // (2,16,16)
    const float* __restrict__ h0f, const float* __restrict__ h0b,
    float* __restrict__ ys,          // (2,N,16)
    float* __restrict__ hfin)        // 512 floats: new_fwd then new_bwd
{
    const int dir = blockIdx.y;
    const int chunk = blockIdx.x;
    const int tid = threadIdx.x;
    const int i = tid >> 4, j = tid & 15;
    const int lane = tid & 31;
    const int srcRot  = (lane & 16) | ((lane + 15) & 15);  // j-1 mod 16 in 16-lane group
    const int srcRot2 = (lane & 16) | ((lane + 14) & 15);  // j-2 mod 16

    __shared__ float s_inWx[8][16];   // [m][i]
    __shared__ float s_dtWT[16][16];  // [k][i]
    __shared__ float s_BWT[16][16];   // [k][j]
    __shared__ float s_CWT[16][16];
    __shared__ float s_dtb[16];
    __shared__ float sx[16][8];
    __shared__ float sxb[16][16];
    __shared__ float sdt[16][16];
    __shared__ float sdxb[16][16];
    __shared__ float sB[16][16];
    __shared__ float sC[16][16];
    __shared__ float sh[16][16][17];  // padded: conflict-free write(t,i,j) & read(j-loop)

    if (tid < 128) { int m = tid >> 4, c = tid & 15; s_inWx[m][c] = inW[dir * 256 + c * 8 + m]; }
    { int k = tid >> 4, c = tid & 15;
      s_dtWT[k][c] = dtW[dir * 256 + c * 16 + k];
      s_BWT[k][c]  = BW [dir * 256 + c * 16 + k];
      s_CWT[k][c]  = CW [dir * 256 + c * 16 + k]; }
    if (tid < 16) s_dtb[tid] = dtb[dir * 16 + tid];

    const float Ac = -__expf(Alog[dir * 256 + tid]);
    const float Rc = rope[dir * 256 + tid];

    int g0 = chunk * L_CH - WARMUP;
    float h;
    if (g0 <= 0) { g0 = 0; h = (dir == 0 ? h0f : h0b)[tid]; }  // exact initial state
    else h = 0.0f;                                             // warmup (state decays)
    const int gend = (chunk + 1) * L_CH;
    const int outStart = chunk * L_CH;

    const int xt = tid >> 3, xm = tid & 7;   // staging role for tid<128
    float xr = 0.0f;
    if (tid < 128) {
        int p = (dir == 0) ? (g0 + xt) : (NTOT - 1 - (g0 + xt));
        xr = x[p * 8 + xm];
    }
    __syncthreads();

    for (int base = g0; base < gend; base += 16) {
        const bool doOut = (base >= outStart);   // block-uniform
        if (tid < 128) sx[xt][xm] = xr;
        __syncthreads();                                         // S1
        {   // xb projection
            int t = tid >> 4, c = tid & 15;
            float acc = 0.0f;
#pragma unroll
            for (int m = 0; m < 8; m++) acc = fmaf(sx[t][m], s_inWx[m][c], acc);
            sxb[t][c] = acc;
        }
        __syncthreads();                                         // S2
        {   // dt / B (+C for output tiles) projections
            int t = tid >> 4, c = tid & 15;
            float u = s_dtb[c], bv = 0.0f;
#pragma unroll
            for (int k = 0; k < 16; k++) {
                float xbk = sxb[t][k];
                u  = fmaf(xbk, s_dtWT[k][c], u);
                bv = fmaf(xbk, s_BWT[k][c], bv);
            }
            // fast softplus: MUFU exp+log; u>15 branch keeps overflow exact
            float dt = (u > 15.0f) ? u : __logf(1.0f + __expf(u));
            sdt[t][c] = dt;
            sdxb[t][c] = dt * sxb[t][c];
            sB[t][c] = bv;
            if (doOut) {
                float cv = 0.0f;
#pragma unroll
                for (int k = 0; k < 16; k++) cv = fmaf(sxb[t][k], s_CWT[k][c], cv);
                sC[t][c] = cv;
            }
        }
        // prefetch next tile's x (latency hidden behind phases B/C/D)
        if (tid < 128 && base + 16 < gend) {
            int p = (dir == 0) ? (base + 16 + xt) : (NTOT - 1 - (base + 16 + xt));
            xr = x[p * 8 + xm];
        }
        __syncthreads();                                         // S3
        // ---- phases B+C in two halves of 4 two-step rounds each ----
#pragma unroll
        for (int half = 0; half < 2; half++) {
            float cA[4], cB[4], cC[4], cD[4];   // 2-step jump coefs
            float a0[4], b0[4], d0[4];          // step-t0 base coefs (side branch)
#pragma unroll
            for (int rr = 0; rr < 4; rr++) {
                int t0 = (half * 4 + rr) * 2, t1 = t0 + 1;
                float dt0 = sdt[t0][i], dt1 = sdt[t1][i];
                float sn0, cs0, sn1, cs1;
                __sincosf(dt0 * Rc, &sn0, &cs0);
                __sincosf(dt1 * Rc, &sn1, &cs1);
                float x0 = dt0 * Ac, x1 = dt1 * Ac;
                float r0 = __fdividef(fmaf(0.5f, x0, 1.0f), fmaf(-0.5f, x0, 1.0f + 1e-8f));
                float r1 = __fdividef(fmaf(0.5f, x1, 1.0f), fmaf(-0.5f, x1, 1.0f + 1e-8f));
                float ca0 = cs0 * r0, cb0 = sn0 * r0;
                float ca1 = cs1 * r1, cb1 = sn1 * r1;
                float db0 = sdxb[t0][i] * sB[t0][j];
                float db1 = sdxb[t1][i] * sB[t1][j];
                float ca0m = __shfl_sync(0xffffffffu, ca0, srcRot);
                float cb0m = __shfl_sync(0xffffffffu, cb0, srcRot);
                float db0m = __shfl_sync(0xffffffffu, db0, srcRot);
                cA[rr] = ca1 * ca0;
                cB[rr] = -fmaf(ca1, cb0, cb1 * ca0m);
                cC[rr] = cb1 * cb0m;
                cD[rr] = fmaf(ca1, db0, fmaf(-cb1, db0m, db1));
                a0[rr] = ca0; b0[rr] = cb0; d0[rr] = db0;
            }
            if (doOut) {
#pragma unroll
                for (int rr = 0; rr < 4; rr++) {
                    float hm1 = __shfl_sync(0xffffffffu, h, srcRot);
                    float hm2 = __shfl_sync(0xffffffffu, h, srcRot2);
                    float hs = fmaf(a0[rr], h, fmaf(-b0[rr], hm1, d0[rr]));
                    h = fmaf(cA[rr], h, fmaf(cB[rr], hm1, fmaf(cC[rr], hm2, cD[rr])));
                    int t0 = (half * 4 + rr) * 2;
                    sh[t0][i][j] = hs;
                    sh[t0 + 1][i][j] = h;
                }
            } else {
#pragma unroll
                for (int rr = 0; rr < 4; rr++) {
                    float hm1 = __shfl_sync(0xffffffffu, h, srcRot);
                    float hm2 = __shfl_sync(0xffffffffu, h, srcRot2);
                    h = fmaf(cA[rr], h, fmaf(cB[rr], hm1, fmaf(cC[rr], hm2, cD[rr])));
                }
            }
        }
        if (doOut) {
            __syncthreads();                                     // S4
            // ---- phase D: y = sum_j h*C, fully parallel ----
            int t = tid >> 4, ii = tid & 15;
            float acc = 0.0f;
#pragma unroll
            for (int jj = 0; jj < 16; jj++)
                acc = fmaf(sh[t][ii][jj], sC[t][jj], acc);
            int p = (dir == 0) ? (base + t) : (NTOT - 1 - (base + t));
            ys[((size_t)dir * NTOT + p) * 16 + ii] = acc;
        }
        // no trailing sync: next tile's S1 orders all cross-tile hazards
    }
    if (chunk == NCH - 1) hfin[dir * 256 + tid] = h;  // final states (outputs)
}

// ---------------- kernel 4: FUSED epilogue + GRU + PEER (sorted order, scattered out) ----
__global__ void __launch_bounds__(256) postgp_kernel(
    const float* __restrict__ x, const float* __restrict__ ys,
    const unsigned int* __restrict__ sidx,
    const float* __restrict__ inW, const float* __restrict__ D,
    const float* __restrict__ outW,
    const float* __restrict__ g, const float* __restrict__ s,
    const float* __restrict__ gru0,
    const float* __restrict__ Wz, const float* __restrict__ bz,
    const float* __restrict__ Wr, const float* __restrict__ br,
    const float* __restrict__ Wh, const float* __restrict__ bh,
    const float* __restrict__ qW, const float* __restrict__ kA, const float* __restrict__ kB,
    const float* __restrict__ eW1, const float* __restrict__ eb1,
    const float* __restrict__ eW2, const float* __restrict__ eb2,
    float* __restrict__ out) {
    __shared__ float sWz[88], sWr[88], sWh[88], sbz[4], sbr[4], sbh[4];
    __shared__ float sqW[704];       // (4,8,22)
    __shared__ float skA[192], skB[192];
    __shared__ float seW1[144 * 17], seb1[144 * 17], seW2[144 * 17];  // pad vs bank conflicts
    __shared__ float seb2[144];
    __shared__ float sinW[512];      // (2,32,8)
    __shared__ float soutW[256];     // (2,8,16)
    __shared__ float sD[32];

    int tid = threadIdx.x;
    for (int q = tid; q < 88; q += 256) { sWz[q] = Wz[q]; sWr[q] = Wr[q]; sWh[q] = Wh[q]; }
    if (tid < 4) { sbz[tid] = bz[tid]; sbr[tid] = br[tid]; sbh[tid] = bh[tid]; }
    for (int q = tid; q < 704; q += 256) sqW[q] = qW[q];
    for (int q = tid; q < 192; q += 256) { skA[q] = kA[q]; skB[q] = kB[q]; }
    for (int q = tid; q < 2304; q += 256) {
        int e = q >> 4, eh = q & 15;
        seW1[e * 17 + eh] = eW1[q];
        seb1[e * 17 + eh] = eb1[q];
        seW2[e * 17 + eh] = eW2[q];
    }
    for (int q = tid; q < 144; q += 256) seb2[q] = eb2[q];
    for (int q = tid; q < 512; q += 256) sinW[q] = inW[q];
    if (tid < 256) soutW[tid] = outW[tid];
    if (tid < 32) sD[tid] = D[tid];
    __syncthreads();

    int k = blockIdx.x * blockDim.x + tid;   // SORTED position
    int o = sidx[k];                          // original index

    // ---- epilogue: ctx for both directions, in registers ----
    float4 xv0 = ((const float4*)x)[k * 2 + 0];
    float4 xv1 = ((const float4*)x)[k * 2 + 1];
    float xv[8] = {xv0.x, xv0.y, xv0.z, xv0.w, xv1.x, xv1.y, xv1.z, xv1.w};
    float xin[18];
#pragma unroll
    for (int d = 0; d < 2; d++) {
        float yv[16];
#pragma unroll
        for (int q = 0; q < 4; q++) {
            float4 y4 = ((const float4*)ys)[((size_t)d * NTOT + k) * 4 + q];
            yv[q * 4 + 0] = y4.x; yv[q * 4 + 1] = y4.y;
            yv[q * 4 + 2] = y4.z; yv[q * 4 + 3] = y4.w;
        }
        float acc[8];
#pragma unroll
        for (int m = 0; m < 8; m++) acc[m] = 0.0f;
#pragma unroll
        for (int ii = 0; ii < 16; ii++) {
            float xb = 0.0f, z = 0.0f;
#pragma unroll
            for (int m = 0; m < 8; m++) {
                xb = fmaf(xv[m], sinW[d * 256 + ii * 8 + m], xb);
                z  = fmaf(xv[m], sinW[d * 256 + (16 + ii) * 8 + m], z);
            }
            float sg = __fdividef(1.0f, 1.0f + __expf(-z));
            float yi = fmaf(yv[ii], z * sg, sD[d * 16 + ii] * xb);
#pragma unroll
            for (int m = 0; m < 8; m++)
                acc[m] = fmaf(yi, soutW[d * 128 + m * 16 + ii], acc[m]);
        }
#pragma unroll
        for (int m = 0; m < 8; m++) xin[2 + d * 8 + m] = acc[m];
    }

    // ---- GRU + PEER at original index o ----
    float gv = g[o], sv = s[o];
    xin[0] = gv; xin[1] = sv;
    float4 h4 = ((const float4*)gru0)[o];
    float hv[4] = {h4.x, h4.y, h4.z, h4.w};

    float zg[4], rr[4];
#pragma unroll
    for (int c = 0; c < 4; c++) {
        float az = sbz[c], ar = sbr[c];
#pragma unroll
        for (int q = 0; q < 18; q++) { az = fmaf(xin[q], sWz[c * 22 + q], az); ar = fmaf(xin[q], sWr[c * 22 + q], ar); }
#pragma unroll
        for (int q = 0; q < 4; q++) { az = fmaf(hv[q], sWz[c * 22 + 18 + q], az); ar = fmaf(hv[q], sWr[c * 22 + 18 + q], ar); }
        zg[c] = __fdividef(1.0f, 1.0f + __expf(-az));
        rr[c] = __fdividef(1.0f, 1.0f + __expf(-ar));
    }
    float ng[4];
#pragma unroll
    for (int c = 0; c < 4; c++) {
        float ah = sbh[c];
#pragma unroll
        for (int q = 0; q < 18; q++) ah = fmaf(xin[q], sWh[c * 22 + q], ah);
#pragma unroll
        for (int q = 0; q < 4; q++) ah = fmaf(rr[q] * hv[q], sWh[c * 22 + 18 + q], ah);
        float ht = tanhf(ah);
        ng[c] = fmaf(zg[c], ht - hv[c], hv[c]);
    }
    ((float4*)(out + NTOT))[o] = make_float4(ng[0], ng[1], ng[2], ng[3]);

    float pin[22];
#pragma unroll
    for (int c = 0; c < 4; c++) pin[c] = ng[c];
#pragma unroll
    for (int m = 0; m < 16; m++) pin[4 + m] = xin[2 + m];
    pin[20] = gv; pin[21] = sv;

    float tot = 0.0f;
#pragma unroll
    for (int hd = 0; hd < 4; hd++) {
        float q[8];
#pragma unroll
        for (int m = 0; m < 8; m++) {
            float a = 0.0f;
#pragma unroll
            for (int qq = 0; qq < 22; qq++) a = fmaf(pin[qq], sqW[hd * 176 + m * 22 + qq], a);
            q[m] = a;
        }
        int ia = 0, ib = 0;
        float ba = -3.4e38f, bb = -3.4e38f;
#pragma unroll
        for (int p = 0; p < 12; p++) {
            float sa = q[0] * skA[hd * 48 + p * 4 + 0];
            sa = fmaf(q[1], skA[hd * 48 + p * 4 + 1], sa);
            sa = fmaf(q[2], skA[hd * 48 + p * 4 + 2], sa);
            sa = fmaf(q[3], skA[hd * 48 + p * 4 + 3], sa);
            if (sa > ba) { ba = sa; ia = p; }
            float sb = q[4] * skB[hd * 48 + p * 4 + 0];
            sb = fmaf(q[5], skB[hd * 48 + p * 4 + 1], sb);
            sb = fmaf(q[6], skB[hd * 48 + p * 4 + 2], sb);
            sb = fmaf(q[7], skB[hd * 48 + p * 4 + 3], sb);
            if (sb > bb) { bb = sb; ib = p; }
        }
        int e = ia * 12 + ib;
        float acc = seb2[e];
#pragma unroll
        for (int eh = 0; eh < 16; eh++) {
            float z1 = fmaf(seW1[e * 17 + eh], gv, seb1[e * 17 + eh]);
            z1 = fmaxf(z1, 0.0f);
            acc = fmaf(seW2[e * 17 + eh], z1, acc);
        }
        tot += acc;
    }
    out[o] = fmaf(0.1f * 0.25f, tot, gv);  // g + RESCALE * total/NH
}

// ---------------- launch ----------------
extern "C" void kernel_launch(void* const* d_in, const int* in_sizes, int n_in,
                              void* d_out, int out_size) {
    const float* grad      = (const float*)d_in[0];
    const float* sharp     = (const float*)d_in[1];
    const float* gru_state = (const float*)d_in[2];
    const float* mfwd      = (const float*)d_in[3];
    const float* mbwd      = (const float*)d_in[4];
    const float* inproj_W  = (const float*)d_in[5];
    const float* inproj_b  = (const float*)d_in[6];
    const float* m_inW     = (const float*)d_in[7];
    const float* m_dtW     = (const float*)d_in[8];
    const float* m_dtb     = (const float*)d_in[9];
    const float* m_BW      = (const float*)d_in[10];
    const float* m_CW      = (const float*)d_in[11];
    const float* m_Alog    = (const float*)d_in[12];
    const float* m_D       = (const float*)d_in[13];
    const float* m_rope    = (const float*)d_in[14];
    const float* m_outW    = (const float*)d_in[15];
    const float* gru_Wz    = (const float*)d_in[16];
    const float* gru_bz    = (const float*)d_in[17];
    const float* gru_Wr    = (const float*)d_in[18];
    const float* gru_br    = (const float*)d_in[19];
    const float* gru_Wh    = (const float*)d_in[20];
    const float* gru_bh    = (const float*)d_in[21];
    const float* peer_qW   = (const float*)d_in[22];
    const float* keysA     = (const float*)d_in[23];
    const float* keysB     = (const float*)d_in[24];
    const float* eW1       = (const float*)d_in[25];
    const float* eb1       = (const float*)d_in[26];
    const float* eW2       = (const float*)d_in[27];
    const float* eb2       = (const float*)d_in[28];
    float* out = (float*)d_out;

    unsigned int *ki, *ko, *vi, *vo;
    void* tmp;
    float *xbuf, *ysbuf;
    cudaGetSymbolAddress((void**)&ki, g_keys);
    cudaGetSymbolAddress((void**)&ko, g_keys2);
    cudaGetSymbolAddress((void**)&vi, g_idx);
    cudaGetSymbolAddress((void**)&vo, g_idx2);
    cudaGetSymbolAddress(&tmp, g_cubtemp);
    cudaGetSymbolAddress((void**)&xbuf, g_x);
    cudaGetSymbolAddress((void**)&ysbuf, g_ys);

    prep_kernel<<<NTOT / 256, 256>>>(grad, ki, vi);

    // FULL 32-bit stable sort via CUB: permutation must exactly match jnp.argsort.
    size_t temp_bytes = sizeof(g_cubtemp);
    cub::DeviceRadixSort::SortPairs(tmp, temp_bytes, ki, ko, vi, vo, NTOT, 0, 32,
                                    (cudaStream_t)0);

    xproj_kernel<<<NTOT / 256, 256>>>(grad, sharp, vo, inproj_W, inproj_b, xbuf);

    scan_kernel<<<dim3(NCH, 2), 256>>>(xbuf, m_inW, m_dtW, m_dtb, m_BW, m_CW,
                                       m_Alog, m_rope, mfwd, mbwd, ysbuf,
                                       out + 5 * NTOT);

    postgp_kernel<<<NTOT / 256, 256>>>(xbuf, ysbuf, vo, m_inW, m_D, m_outW,
                                       grad, sharp, gru_state,
                                       gru_Wz, gru_bz, gru_Wr, gru_br, gru_Wh, gru_bh,
                                       peer_qW, keysA, keysB, eW1, eb1, eW2, eb2, out);

    (void)in_sizes; (void)n_in; (void)out_size;
}

// round 16
// speedup vs baseline: 2.0194x; 1.1118x over previous
#include <cuda_runtime.h>
#include <cuda_bf16.h>
#include <cub/cub.cuh>
#include <math.h>

#define NTOT 65536
#define L_CH 256
#define WARMUP 32
#define NCH (NTOT / L_CH)   // 256

// ---------------- static scratch (no allocations allowed) ----------------
__device__ unsigned int g_keys[NTOT];
__device__ unsigned int g_keys2[NTOT];
__device__ unsigned int g_idx[NTOT];
__device__ unsigned int g_idx2[NTOT];
__device__ unsigned char g_cubtemp[1 << 23];   // 8 MB, plenty for 64K pairs
__device__ float g_ys[2 * NTOT * 16];          // raw scan outputs (dir, sortedpos, i)

// ---------------- kernel 1: sort keys ----------------
__global__ void prep_kernel(const float* __restrict__ g,
                            unsigned int* __restrict__ keys,
                            unsigned int* __restrict__ vals) {
    int n = blockIdx.x * blockDim.x + threadIdx.x;
    keys[n] = __float_as_uint(g[n]) & 0x7fffffffu;  // |g| bits sort as uint
    vals[n] = (unsigned)n;
}

// ---------------- kernel 2: chunked warmup Mamba scan (both directions) ----------------
// xproj is FUSED into staging: 128 staging threads gather g/s through sidx
// (prefetched one tile ahead) and apply the 8x2 inproj in registers.
// Per 16-step tile:
//   A) parallel projections (xb, dt, B[, C]) with 256 threads as (t,c)
//   B) per-(i,j) 1-step coefficients (MUFU sincos + fast div), off the chain
//   C) tight recurrence: shfl + 2 FMA (+ STS h when producing output)
//   D) parallel y = sum_j h*C from shared (output tiles only)
__global__ void __launch_bounds__(256) scan_kernel(
    const float* __restrict__ g, const float* __restrict__ s,
    const unsigned int* __restrict__ sidx,
    const float* __restrict__ pW,    // inproj_W (8,2)
    const float* __restrict__ pb,    // inproj_b (8)
    const float* __restrict__ inW,   // (2,32,8)
    const float* __restrict__ dtW,   // (2,16,16)
    const float* __restrict__ dtb,   // (2,16)
    const float* __restrict__ BW,    // (2,16,16)
    const float* __restrict__ CW,    // (2,16,16)
    const float* __restrict__ Alog,  // (2,16,16)
    const float* __restrict__ rope,  // (2,16,16)
    const float* __restrict__ h0f, const float* __restrict__ h0b,
    float* __restrict__ ys,          // (2,N,16)
    float* __restrict__ hfin)        // 512 floats: new_fwd then new_bwd
{
    const int dir = blockIdx.y;
    const int chunk = blockIdx.x;
    const int tid = threadIdx.x;
    const int i = tid >> 4, j = tid & 15;
    const int lane = tid & 31;
    const int srcRot = (lane & 16) | ((lane + 15) & 15);  // j-1 mod 16 in 16-lane group

    __shared__ float s_inWx[8][16];   // [m][i]
    __shared__ float s_dtWT[16][16];  // [k][i]
    __shared__ float s_BWT[16][16];   // [k][j]
    __shared__ float s_CWT[16][16];
    __shared__ float s_dtb[16];
    __shared__ float sx[16][8];
    __shared__ float sxb[16][16];
    __shared__ float sdt[16][16];
    __shared__ float sdxb[16][16];
    __shared__ float sB[16][16];
    __shared__ float sC[16][16];
    __shared__ float sh[16][16][17];  // padded: conflict-free write(t,i,j) & read(j-loop)

    if (tid < 128) { int m = tid >> 4, c = tid & 15; s_inWx[m][c] = inW[dir * 256 + c * 8 + m]; }
    { int k = tid >> 4, c = tid & 15;
      s_dtWT[k][c] = dtW[dir * 256 + c * 16 + k];
      s_BWT[k][c]  = BW [dir * 256 + c * 16 + k];
      s_CWT[k][c]  = CW [dir * 256 + c * 16 + k]; }
    if (tid < 16) s_dtb[tid] = dtb[dir * 16 + tid];

    const float Ac = -__expf(Alog[dir * 256 + tid]);
    const float Rc = rope[dir * 256 + tid];

    int g0 = chunk * L_CH - WARMUP;
    float h;
    if (g0 <= 0) { g0 = 0; h = (dir == 0 ? h0f : h0b)[tid]; }  // exact initial state
    else h = 0.0f;                                             // warmup (state decays)
    const int gend = (chunk + 1) * L_CH;
    const int outStart = chunk * L_CH;

    // staging role (tid<128): (t,m) = (tid>>3, tid&7); inproj in registers
    const int xt = tid >> 3, xm = tid & 7;
    float wm0 = 0.0f, wm1 = 0.0f, bm = 0.0f;
    float grv = 0.0f, srv = 0.0f;
    if (tid < 128) {
        wm0 = pW[xm * 2 + 0]; wm1 = pW[xm * 2 + 1]; bm = pb[xm];
        int p = (dir == 0) ? (g0 + xt) : (NTOT - 1 - (g0 + xt));
        int o = sidx[p];
        grv = g[o]; srv = s[o];
    }
    __syncthreads();

    for (int base = g0; base < gend; base += 16) {
        const bool doOut = (base >= outStart);   // block-uniform
        if (tid < 128) sx[xt][xm] = fmaf(grv, wm0, fmaf(srv, wm1, bm));
        __syncthreads();                                         // S1
        {   // xb projection
            int t = tid >> 4, c = tid & 15;
            float acc = 0.0f;
#pragma unroll
            for (int m = 0; m < 8; m++) acc = fmaf(sx[t][m], s_inWx[m][c], acc);
            sxb[t][c] = acc;
        }
        __syncthreads();                                         // S2
        {   // dt / B (+C for output tiles) projections
            int t = tid >> 4, c = tid & 15;
            float u = s_dtb[c], bv = 0.0f;
#pragma unroll
            for (int k = 0; k < 16; k++) {
                float xbk = sxb[t][k];
                u  = fmaf(xbk, s_dtWT[k][c], u);
                bv = fmaf(xbk, s_BWT[k][c], bv);
            }
            // fast softplus: MUFU exp+log; u>15 branch keeps overflow exact
            float dt = (u > 15.0f) ? u : __logf(1.0f + __expf(u));
            sdt[t][c] = dt;
            sdxb[t][c] = dt * sxb[t][c];
            sB[t][c] = bv;
            if (doOut) {
                float cv = 0.0f;
#pragma unroll
                for (int k = 0; k < 16; k++) cv = fmaf(sxb[t][k], s_CWT[k][c], cv);
                sC[t][c] = cv;
            }
        }
        // prefetch next tile's g/s (sidx -> g/s chain hidden behind B/C/D)
        if (tid < 128 && base + 16 < gend) {
            int p = (dir == 0) ? (base + 16 + xt) : (NTOT - 1 - (base + 16 + xt));
            int o = sidx[p];
            grv = g[o]; srv = s[o];
        }
        __syncthreads();                                         // S3
        // ---- phases B+C in two 8-step halves (low register pressure) ----
#pragma unroll
        for (int half = 0; half < 2; half++) {
            float ca[8], cb[8], db[8];
#pragma unroll
            for (int tt = 0; tt < 8; tt++) {
                int t = half * 8 + tt;
                float dt = sdt[t][i];
                float ph = dt * Rc;
                float sn, cs;
                __sincosf(ph, &sn, &cs);        // |ph| small: abs err ~2^-21
                float xA  = dt * Ac;
                float num = fmaf(0.5f, xA, 1.0f);
                float den = fmaf(-0.5f, xA, 1.0f + 1e-8f);
                float t_r = __fdividef(num, den);
                ca[tt] = cs * t_r;
                cb[tt] = sn * t_r;
                db[tt] = sdxb[t][i] * sB[t][j];
            }
            if (doOut) {
#pragma unroll
                for (int tt = 0; tt < 8; tt++) {
                    float hm1 = __shfl_sync(0xffffffffu, h, srcRot);
                    h = fmaf(ca[tt], h, fmaf(-cb[tt], hm1, db[tt]));
                    sh[half * 8 + tt][i][j] = h;
                }
            } else {
#pragma unroll
                for (int tt = 0; tt < 8; tt++) {
                    float hm1 = __shfl_sync(0xffffffffu, h, srcRot);
                    h = fmaf(ca[tt], h, fmaf(-cb[tt], hm1, db[tt]));
                }
            }
        }
        if (doOut) {
            __syncthreads();                                     // S4
            // ---- phase D: y = sum_j h*C, fully parallel ----
            int t = tid >> 4, ii = tid & 15;
            float acc = 0.0f;
#pragma unroll
            for (int jj = 0; jj < 16; jj++)
                acc = fmaf(sh[t][ii][jj], sC[t][jj], acc);
            int p = (dir == 0) ? (base + t) : (NTOT - 1 - (base + t));
            ys[((size_t)dir * NTOT + p) * 16 + ii] = acc;
        }
        // no trailing sync: next tile's S1 orders all cross-tile hazards
    }
    if (chunk == NCH - 1) hfin[dir * 256 + tid] = h;  // final states (outputs)
}

// ---------------- kernel 3: FUSED epilogue + GRU + PEER (sorted order, scattered out) ----
__global__ void __launch_bounds__(256) postgp_kernel(
    const float* __restrict__ ys,
    const unsigned int* __restrict__ sidx,
    const float* __restrict__ pW, const float* __restrict__ pb,
    const float* __restrict__ inW, const float* __restrict__ D,
    const float* __restrict__ outW,
    const float* __restrict__ g, const float* __restrict__ s,
    const float* __restrict__ gru0,
    const float* __restrict__ Wz, const float* __restrict__ bz,
    const float* __restrict__ Wr, const float* __restrict__ br,
    const float* __restrict__ Wh, const float* __restrict__ bh,
    const float* __restrict__ qW, const float* __restrict__ kA, const float* __restrict__ kB,
    const float* __restrict__ eW1, const float* __restrict__ eb1,
    const float* __restrict__ eW2, const float* __restrict__ eb2,
    float* __restrict__ out) {
    __shared__ float sWz[88], sWr[88], sWh[88], sbz[4], sbr[4], sbh[4];
    __shared__ float sqW[704];       // (4,8,22)
    __shared__ float skA[192], skB[192];
    __shared__ float seW1[144 * 17], seb1[144 * 17], seW2[144 * 17];  // pad vs bank conflicts
    __shared__ float seb2[144];
    __shared__ float sinW[512];      // (2,32,8)
    __shared__ float soutW[256];     // (2,8,16)
    __shared__ float sD[32];
    __shared__ float spW[16], spb[8];

    int tid = threadIdx.x;
    for (int q = tid; q < 88; q += 256) { sWz[q] = Wz[q]; sWr[q] = Wr[q]; sWh[q] = Wh[q]; }
    if (tid < 4) { sbz[tid] = bz[tid]; sbr[tid] = br[tid]; sbh[tid] = bh[tid]; }
    for (int q = tid; q < 704; q += 256) sqW[q] = qW[q];
    for (int q = tid; q < 192; q += 256) { skA[q] = kA[q]; skB[q] = kB[q]; }
    for (int q = tid; q < 2304; q += 256) {
        int e = q >> 4, eh = q & 15;
        seW1[e * 17 + eh] = eW1[q];
        seb1[e * 17 + eh] = eb1[q];
        seW2[e * 17 + eh] = eW2[q];
    }
    for (int q = tid; q < 144; q += 256) seb2[q] = eb2[q];
    for (int q = tid; q < 512; q += 256) sinW[q] = inW[q];
    if (tid < 256) soutW[tid] = outW[tid];
    if (tid < 32) sD[tid] = D[tid];
    if (tid < 16) spW[tid] = pW[tid];
    if (tid < 8)  spb[tid] = pb[tid];
    __syncthreads();

    int k = blockIdx.x * blockDim.x + tid;   // SORTED position
    int o = sidx[k];                          // original index
    float gv = g[o], sv = s[o];

    // ---- recompute x (identical inproj expression to scan staging) ----
    float xv[8];
#pragma unroll
    for (int m = 0; m < 8; m++)
        xv[m] = fmaf(gv, spW[m * 2 + 0], fmaf(sv, spW[m * 2 + 1], spb[m]));

    // ---- epilogue: ctx for both directions, in registers ----
    float xin[18];
#pragma unroll
    for (int d = 0; d < 2; d++) {
        float yv[16];
#pragma unroll
        for (int q = 0; q < 4; q++) {
            float4 y4 = ((const float4*)ys)[((size_t)d * NTOT + k) * 4 + q];
            yv[q * 4 + 0] = y4.x; yv[q * 4 + 1] = y4.y;
            yv[q * 4 + 2] = y4.z; yv[q * 4 + 3] = y4.w;
        }
        float acc[8];
#pragma unroll
        for (int m = 0; m < 8; m++) acc[m] = 0.0f;
#pragma unroll
        for (int ii = 0; ii < 16; ii++) {
            float xb = 0.0f, z = 0.0f;
#pragma unroll
            for (int m = 0; m < 8; m++) {
                xb = fmaf(xv[m], sinW[d * 256 + ii * 8 + m], xb);
                z  = fmaf(xv[m], sinW[d * 256 + (16 + ii) * 8 + m], z);
            }
            float sg = __fdividef(1.0f, 1.0f + __expf(-z));
            float yi = fmaf(yv[ii], z * sg, sD[d * 16 + ii] * xb);
#pragma unroll
            for (int m = 0; m < 8; m++)
                acc[m] = fmaf(yi, soutW[d * 128 + m * 16 + ii], acc[m]);
        }
#pragma unroll
        for (int m = 0; m < 8; m++) xin[2 + d * 8 + m] = acc[m];
    }

    // ---- GRU + PEER at original index o ----
    xin[0] = gv; xin[1] = sv;
    float4 h4 = ((const float4*)gru0)[o];
    float hv[4] = {h4.x, h4.y, h4.z, h4.w};

    float zg[4], rr[4];
#pragma unroll
    for (int c = 0; c < 4; c++) {
        float az = sbz[c], ar = sbr[c];
#pragma unroll
        for (int q = 0; q < 18; q++) { az = fmaf(xin[q], sWz[c * 22 + q], az); ar = fmaf(xin[q], sWr[c * 22 + q], ar); }
#pragma unroll
        for (int q = 0; q < 4; q++) { az = fmaf(hv[q], sWz[c * 22 + 18 + q], az); ar = fmaf(hv[q], sWr[c * 22 + 18 + q], ar); }
        zg[c] = __fdividef(1.0f, 1.0f + __expf(-az));
        rr[c] = __fdividef(1.0f, 1.0f + __expf(-ar));
    }
    float ng[4];
#pragma unroll
    for (int c = 0; c < 4; c++) {
        float ah = sbh[c];
#pragma unroll
        for (int q = 0; q < 18; q++) ah = fmaf(xin[q], sWh[c * 22 + q], ah);
#pragma unroll
        for (int q = 0; q < 4; q++) ah = fmaf(rr[q] * hv[q], sWh[c * 22 + 18 + q], ah);
        float ht = tanhf(ah);
        ng[c] = fmaf(zg[c], ht - hv[c], hv[c]);
    }
    ((float4*)(out + NTOT))[o] = make_float4(ng[0], ng[1], ng[2], ng[3]);

    float pin[22];
#pragma unroll
    for (int c = 0; c < 4; c++) pin[c] = ng[c];
#pragma unroll
    for (int m = 0; m < 16; m++) pin[4 + m] = xin[2 + m];
    pin[20] = gv; pin[21] = sv;

    float tot = 0.0f;
#pragma unroll
    for (int hd = 0; hd < 4; hd++) {
        float q[8];
#pragma unroll
        for (int m = 0; m < 8; m++) {
            float a = 0.0f;
#pragma unroll
            for (int qq = 0; qq < 22; qq++) a = fmaf(pin[qq], sqW[hd * 176 + m * 22 + qq], a);
            q[m] = a;
        }
        int ia = 0, ib = 0;
        float ba = -3.4e38f, bb = -3.4e38f;
#pragma unroll
        for (int p = 0; p < 12; p++) {
            float sa = q[0] * skA[hd * 48 + p * 4 + 0];
            sa = fmaf(q[1], skA[hd * 48 + p * 4 + 1], sa);
            sa = fmaf(q[2], skA[hd * 48 + p * 4 + 2], sa);
            sa = fmaf(q[3], skA[hd * 48 + p * 4 + 3], sa);
            if (sa > ba) { ba = sa; ia = p; }
            float sb = q[4] * skB[hd * 48 + p * 4 + 0];
            sb = fmaf(q[5], skB[hd * 48 + p * 4 + 1], sb);
            sb = fmaf(q[6], skB[hd * 48 + p * 4 + 2], sb);
            sb = fmaf(q[7], skB[hd * 48 + p * 4 + 3], sb);
            if (sb > bb) { bb = sb; ib = p; }
        }
        int e = ia * 12 + ib;
        float acc = seb2[e];
#pragma unroll
        for (int eh = 0; eh < 16; eh++) {
            float z1 = fmaf(seW1[e * 17 + eh], gv, seb1[e * 17 + eh]);
            z1 = fmaxf(z1, 0.0f);
            acc = fmaf(seW2[e * 17 + eh], z1, acc);
        }
        tot += acc;
    }
    out[o] = fmaf(0.1f * 0.25f, tot, gv);  // g + RESCALE * total/NH
}

// ---------------- launch ----------------
extern "C" void kernel_launch(void* const* d_in, const int* in_sizes, int n_in,
                              void* d_out, int out_size) {
    const float* grad      = (const float*)d_in[0];
    const float* sharp     = (const float*)d_in[1];
    const float* gru_state = (const float*)d_in[2];
    const float* mfwd      = (const float*)d_in[3];
    const float* mbwd      = (const float*)d_in[4];
    const float* inproj_W  = (const float*)d_in[5];
    const float* inproj_b  = (const float*)d_in[6];
    const float* m_inW     = (const float*)d_in[7];
    const float* m_dtW     = (const float*)d_in[8];
    const float* m_dtb     = (const float*)d_in[9];
    const float* m_BW      = (const float*)d_in[10];
    const float* m_CW      = (const float*)d_in[11];
    const float* m_Alog    = (const float*)d_in[12];
    const float* m_D       = (const float*)d_in[13];
    const float* m_rope    = (const float*)d_in[14];
    const float* m_outW    = (const float*)d_in[15];
    const float* gru_Wz    = (const float*)d_in[16];
    const float* gru_bz    = (const float*)d_in[17];
    const float* gru_Wr    = (const float*)d_in[18];
    const float* gru_br    = (const float*)d_in[19];
    const float* gru_Wh    = (const float*)d_in[20];
    const float* gru_bh    = (const float*)d_in[21];
    const float* peer_qW   = (const float*)d_in[22];
    const float* keysA     = (const float*)d_in[23];
    const float* keysB     = (const float*)d_in[24];
    const float* eW1       = (const float*)d_in[25];
    const float* eb1       = (const float*)d_in[26];
    const float* eW2       = (const float*)d_in[27];
    const float* eb2       = (const float*)d_in[28];
    float* out = (float*)d_out;

    unsigned int *ki, *ko, *vi, *vo;
    void* tmp;
    float *ysbuf;
    cudaGetSymbolAddress((void**)&ki, g_keys);
    cudaGetSymbolAddress((void**)&ko, g_keys2);
    cudaGetSymbolAddress((void**)&vi, g_idx);
    cudaGetSymbolAddress((void**)&vo, g_idx2);
    cudaGetSymbolAddress(&tmp, g_cubtemp);
    cudaGetSymbolAddress((void**)&ysbuf, g_ys);

    prep_kernel<<<NTOT / 256, 256>>>(grad, ki, vi);

    // FULL 32-bit stable sort via CUB: permutation must exactly match jnp.argsort.
    size_t temp_bytes = sizeof(g_cubtemp);
    cub::DeviceRadixSort::SortPairs(tmp, temp_bytes, ki, ko, vi, vo, NTOT, 0, 32,
                                    (cudaStream_t)0);

    scan_kernel<<<dim3(NCH, 2), 256>>>(grad, sharp, vo, inproj_W, inproj_b,
                                       m_inW, m_dtW, m_dtb, m_BW, m_CW,
                                       m_Alog, m_rope, mfwd, mbwd, ysbuf,
                                       out + 5 * NTOT);

    postgp_kernel<<<NTOT / 256, 256>>>(ysbuf, vo, inproj_W, inproj_b,
                                       m_inW, m_D, m_outW,
                                       grad, sharp, gru_state,
                                       gru_Wz, gru_bz, gru_Wr, gru_br, gru_Wh, gru_bh,
                                       peer_qW, keysA, keysB, eW1, eb1, eW2, eb2, out);

    (void)in_sizes; (void)n_in; (void)out_size;
}